// round 10
// baseline (speedup 1.0000x reference)
#include <cuda_runtime.h>
#include <cuda_fp16.h>
#include <cstdint>

// Problem constants (fixed by the reference)
#define Bc 128
#define Tc 30
#define Nc 10000
#define Mc 5000
#define Kc 10
#define CHK_W 6
#define OBS_W 50
#define EPSc 1e-6f

#define NTH   768
#define RPC   8              // rows per task buffer
#define NCH   4              // tasks per b (last has 6 rows)
#define NQ    2500           // float4 groups per row
#define NTASKS (Bc * NCH)    // 512 tasks
#define GRID  148            // persistent: one CTA per SM

// (128/127)^6 and (128/127)^50 de-scaling constants
#define SC6   1.04818341f
#define SC50  1.48016639f

// Shared memory layout (bytes)
#define OFF_BUF0 0
#define SZ_BUF   (Nc * 8)                    // 80000: uint2/pos = 8 biased-u8 rows
#define OFF_BUF1 (OFF_BUF0 + SZ_BUF)         // 80000
#define OFF_CA   (OFF_BUF1 + SZ_BUF)         // 160000
#define OFF_CB   (OFF_CA + Mc * 4)           // 180000
#define OFF_CC   (OFF_CB + Mc * 4)           // 200000
#define OFF_OIDX (OFF_CC + Mc * 4)           // 220000
#define OFF_RED  ((OFF_OIDX + Kc * OBS_W * 2 + 15) & ~15)
#define SMEM_BYTES (OFF_RED + 128)           // ~221136

__device__ double g_acc = 0.0;
__device__ unsigned int g_cnt = 0;

__device__ __forceinline__ __half2 H2(unsigned int u) {
    return *reinterpret_cast<const __half2*>(&u);
}
__device__ __forceinline__ unsigned int U2(__half2 h) {
    return *reinterpret_cast<const unsigned int*>(&h);
}
__device__ __forceinline__ unsigned int tanh_h2_u(__half2 v) {
    unsigned int r, x = U2(v);
    asm("tanh.approx.f16x2 %0, %1;" : "=r"(r) : "r"(x));
    return r;
}

// ---- encode: rows (a,b) f32 -> f16x2 word holding integers 1152+round(127*t)
__device__ __forceinline__ unsigned int enc_pair(float a, float b) {
    const __half2 h05  = __float2half2_rn(0.5f);
    const __half2 k127 = __float2half2_rn(127.0f);
    const __half2 b1152= __float2half2_rn(1152.0f);
    __half2 t = H2(tanh_h2_u(__hmul2(__floats2half2_rn(a, b), h05)));
    return U2(__hfma2(t, k127, b1152));
}

// ---- decode: u32 of 4 biased bytes -> two half2 of t*127/128
#define CK   0x64646464u
__device__ __forceinline__ __half2 dec_lo(unsigned int a) {
    const __half2 mk = __float2half2_rn(0.0078125f);   // 2^-7
    const __half2 mb = __float2half2_rn(-9.0f);
    return __hfma2(H2(__byte_perm(a, CK, 0x4140)), mk, mb);
}
__device__ __forceinline__ __half2 dec_hi(unsigned int a) {
    const __half2 mk = __float2half2_rn(0.0078125f);
    const __half2 mb = __float2half2_rn(-9.0f);
    return __hfma2(H2(__byte_perm(a, CK, 0x4342)), mk, mb);
}

// in-flight group of 8 rows x float4
struct G {
    float4 v0, v1, v2, v3, v4, v5, v6, v7;
};

__device__ __forceinline__ void load_group(const float4* __restrict__ rb,
                                           int rows, int q, G& g) {
    const float4 z = make_float4(0.f, 0.f, 0.f, 0.f);
    if (q < NQ) {
        g.v0 =              __ldg(&rb[0 * NQ + q]);
        g.v1 = (rows > 1) ? __ldg(&rb[1 * NQ + q]) : z;
        g.v2 = (rows > 2) ? __ldg(&rb[2 * NQ + q]) : z;
        g.v3 = (rows > 3) ? __ldg(&rb[3 * NQ + q]) : z;
        g.v4 = (rows > 4) ? __ldg(&rb[4 * NQ + q]) : z;
        g.v5 = (rows > 5) ? __ldg(&rb[5 * NQ + q]) : z;
        g.v6 = (rows > 6) ? __ldg(&rb[6 * NQ + q]) : z;
        g.v7 = (rows > 7) ? __ldg(&rb[7 * NQ + q]) : z;
    }
}

__device__ __forceinline__ void encode_store(uint4* __restrict__ bf4, int q, const G& g) {
    if (q < NQ) {
        unsigned int w01x = enc_pair(g.v0.x, g.v1.x), w23x = enc_pair(g.v2.x, g.v3.x);
        unsigned int w45x = enc_pair(g.v4.x, g.v5.x), w67x = enc_pair(g.v6.x, g.v7.x);
        unsigned int w01y = enc_pair(g.v0.y, g.v1.y), w23y = enc_pair(g.v2.y, g.v3.y);
        unsigned int w45y = enc_pair(g.v4.y, g.v5.y), w67y = enc_pair(g.v6.y, g.v7.y);
        unsigned int w01z = enc_pair(g.v0.z, g.v1.z), w23z = enc_pair(g.v2.z, g.v3.z);
        unsigned int w45z = enc_pair(g.v4.z, g.v5.z), w67z = enc_pair(g.v6.z, g.v7.z);
        unsigned int w01w = enc_pair(g.v0.w, g.v1.w), w23w = enc_pair(g.v2.w, g.v3.w);
        unsigned int w45w = enc_pair(g.v4.w, g.v5.w), w67w = enc_pair(g.v6.w, g.v7.w);
        uint4 o0, o1;
        o0.x = __byte_perm(w01x, w23x, 0x6420);
        o0.y = __byte_perm(w45x, w67x, 0x6420);
        o0.z = __byte_perm(w01y, w23y, 0x6420);
        o0.w = __byte_perm(w45y, w67y, 0x6420);
        o1.x = __byte_perm(w01z, w23z, 0x6420);
        o1.y = __byte_perm(w45z, w67z, 0x6420);
        o1.z = __byte_perm(w01w, w23w, 0x6420);
        o1.w = __byte_perm(w45w, w67w, 0x6420);
        bf4[2 * q]     = o0;
        bf4[2 * q + 1] = o1;
    }
}

__device__ __forceinline__ void consume_check(const uint2* __restrict__ buf,
                                              const unsigned int* __restrict__ cA,
                                              const unsigned int* __restrict__ cB,
                                              const unsigned int* __restrict__ cC,
                                              const int* __restrict__ syn,
                                              int m, float& acc) {
    if (m < Mc) {
        unsigned int iA = cA[m];
        unsigned int iB = cB[m];
        unsigned int iC = cC[m];
        uint2 g0 = buf[iA & 0xFFFF];
        uint2 g1 = buf[iA >> 16];
        uint2 g2 = buf[iB & 0xFFFF];
        uint2 g3 = buf[iB >> 16];
        uint2 g4 = buf[iC & 0xFFFF];
        uint2 g5 = buf[iC >> 16];
        const float s  = 1.0f - 2.0f * (float)__ldg(&syn[m]);
        const float sc = s * SC6;

        __half2 p01 = __hmul2(__hmul2(dec_lo(g0.x), dec_lo(g1.x)),
                      __hmul2(__hmul2(dec_lo(g2.x), dec_lo(g3.x)),
                              __hmul2(dec_lo(g4.x), dec_lo(g5.x))));
        __half2 p23 = __hmul2(__hmul2(dec_hi(g0.x), dec_hi(g1.x)),
                      __hmul2(__hmul2(dec_hi(g2.x), dec_hi(g3.x)),
                              __hmul2(dec_hi(g4.x), dec_hi(g5.x))));
        __half2 p45 = __hmul2(__hmul2(dec_lo(g0.y), dec_lo(g1.y)),
                      __hmul2(__hmul2(dec_lo(g2.y), dec_lo(g3.y)),
                              __hmul2(dec_lo(g4.y), dec_lo(g5.y))));
        __half2 p67 = __hmul2(__hmul2(dec_hi(g0.y), dec_hi(g1.y)),
                      __hmul2(__hmul2(dec_hi(g2.y), dec_hi(g3.y)),
                              __hmul2(dec_hi(g4.y), dec_hi(g5.y))));

        float2 f0 = __half22float2(p01);
        float2 f1 = __half22float2(p23);
        float2 f2 = __half22float2(p45);
        float2 f3 = __half22float2(p67);

        float a0 = fmaxf(fmaf(sc, f0.x, 1.0f), EPSc);
        float a1 = fmaxf(fmaf(sc, f0.y, 1.0f), EPSc);
        float a2 = fmaxf(fmaf(sc, f1.x, 1.0f), EPSc);
        float a3 = fmaxf(fmaf(sc, f1.y, 1.0f), EPSc);
        float a4 = fmaxf(fmaf(sc, f2.x, 1.0f), EPSc);
        float a5 = fmaxf(fmaf(sc, f2.y, 1.0f), EPSc);
        float a6 = fmaxf(fmaf(sc, f3.x, 1.0f), EPSc);
        float a7 = fmaxf(fmaf(sc, f3.y, 1.0f), EPSc);
        acc += __log2f((a0 * a1) * (a2 * a3));
        acc += __log2f((a4 * a5) * (a6 * a7));
    }
}

__global__ __launch_bounds__(NTH, 1)
void decode_loss_kernel(const float* __restrict__ llrs,
                        const int* __restrict__ syndromes,
                        const int* __restrict__ observables,
                        const int* __restrict__ chk_idx,
                        const int* __restrict__ obs_idx,
                        float* __restrict__ out) {
    extern __shared__ char smem[];
    uint2*          buf0 = (uint2*)(smem + OFF_BUF0);
    uint2*          buf1 = (uint2*)(smem + OFF_BUF1);
    unsigned int*   cA   = (unsigned int*)(smem + OFF_CA);
    unsigned int*   cB   = (unsigned int*)(smem + OFF_CB);
    unsigned int*   cC   = (unsigned int*)(smem + OFF_CC);
    unsigned short* oidx = (unsigned short*)(smem + OFF_OIDX);
    float*          red  = (float*)(smem + OFF_RED);

    const int cta = blockIdx.x;
    const int tid = threadIdx.x;
    const int ntasks = (NTASKS - cta + GRID - 1) / GRID;

    // ---- Stage index tables (b-independent, once per CTA) ----
    for (int m = tid; m < Mc; m += NTH) {
        const int2* c6 = (const int2*)(chk_idx + 6 * m);
        int2 p0 = __ldg(&c6[0]);
        int2 p1 = __ldg(&c6[1]);
        int2 p2 = __ldg(&c6[2]);
        cA[m] = (unsigned int)p0.x | ((unsigned int)p0.y << 16);
        cB[m] = (unsigned int)p1.x | ((unsigned int)p1.y << 16);
        cC[m] = (unsigned int)p2.x | ((unsigned int)p2.y << 16);
    }
    for (int i = tid; i < Kc * OBS_W; i += NTH)
        oidx[i] = (unsigned short)__ldg(&obs_idx[i]);

    // ---- Prologue: produce task 0 into buf0 (all threads) ----
    {
        const int task0 = cta;
        const int b0 = task0 >> 2, c0 = task0 & 3;
        const int rows0 = min(RPC, Tc - RPC * c0);
        const float4* rb0 = (const float4*)(llrs + ((size_t)b0 * Tc + (size_t)RPC * c0) * Nc);
        uint4* b04 = (uint4*)buf0;
        for (int q = tid; q < NQ; q += NTH) {
            G g;
            load_group(rb0, rows0, q, g);
            encode_store(b04, q, g);
        }
    }
    __syncthreads();

    float acc = 0.0f;

    // ---- Main loop: consume task k while producing task k+1 ----
    for (int k = 0; k < ntasks; k++) {
        const int  taskc = cta + k * GRID;
        const int  bcur  = taskc >> 2;
        const bool nxt   = (k + 1 < ntasks);
        const int  taskn = cta + (k + 1) * GRID;
        const int  bn    = nxt ? (taskn >> 2) : 0;
        const int  cn    = nxt ? (taskn & 3) : 0;
        const int  rowsn = min(RPC, Tc - RPC * cn);
        const float4* rbn = (const float4*)(llrs + ((size_t)bn * Tc + (size_t)RPC * cn) * Nc);

        const uint2* cur  = (k & 1) ? buf1 : buf0;
        uint4*       nxt4 = (uint4*)((k & 1) ? buf0 : buf1);
        const int*   syn  = syndromes + (size_t)bcur * Mc;

        // slice 0: 1 group, 1 check-pass
        {
            G g;
            if (nxt) load_group(rbn, rowsn, tid, g);
            consume_check(cur, cA, cB, cC, syn, tid, acc);
            if (nxt) encode_store(nxt4, tid, g);
        }
        // slice 1: 1 group, 2 check-passes
        {
            G g;
            if (nxt) load_group(rbn, rowsn, tid + NTH, g);
            consume_check(cur, cA, cB, cC, syn, tid + 1 * NTH, acc);
            consume_check(cur, cA, cB, cC, syn, tid + 2 * NTH, acc);
            if (nxt) encode_store(nxt4, tid + NTH, g);
        }
        // slice 2: 1 group, 2 check-passes
        {
            G g;
            if (nxt) load_group(rbn, rowsn, tid + 2 * NTH, g);
            consume_check(cur, cA, cB, cC, syn, tid + 3 * NTH, acc);
            consume_check(cur, cA, cB, cC, syn, tid + 4 * NTH, acc);
            if (nxt) encode_store(nxt4, tid + 2 * NTH, g);
        }
        // slice 3: partial group, 2 check-passes (last partial) + observables
        {
            G g;
            if (nxt) load_group(rbn, rowsn, tid + 3 * NTH, g);
            consume_check(cur, cA, cB, cC, syn, tid + 5 * NTH, acc);
            consume_check(cur, cA, cB, cC, syn, tid + 6 * NTH, acc);
            if (tid < Kc) {
                const __half2 one2 = __float2half2_rn(1.0f);
                __half2 p01 = one2, p23 = one2, p45 = one2, p67 = one2;
                #pragma unroll
                for (int j = 0; j < OBS_W; j++) {
                    uint2 gg = cur[oidx[tid * OBS_W + j]];
                    p01 = __hmul2(p01, dec_lo(gg.x));
                    p23 = __hmul2(p23, dec_hi(gg.x));
                    p45 = __hmul2(p45, dec_lo(gg.y));
                    p67 = __hmul2(p67, dec_hi(gg.y));
                }
                const float s  = 1.0f - 2.0f * (float)__ldg(&observables[(size_t)bcur * Kc + tid]);
                const float sc = s * SC50;
                float2 f0 = __half22float2(p01);
                float2 f1 = __half22float2(p23);
                float2 f2 = __half22float2(p45);
                float2 f3 = __half22float2(p67);
                float a0 = fmaxf(fmaf(sc, f0.x, 1.0f), EPSc);
                float a1 = fmaxf(fmaf(sc, f0.y, 1.0f), EPSc);
                float a2 = fmaxf(fmaf(sc, f1.x, 1.0f), EPSc);
                float a3 = fmaxf(fmaf(sc, f1.y, 1.0f), EPSc);
                float a4 = fmaxf(fmaf(sc, f2.x, 1.0f), EPSc);
                float a5 = fmaxf(fmaf(sc, f2.y, 1.0f), EPSc);
                float a6 = fmaxf(fmaf(sc, f3.x, 1.0f), EPSc);
                float a7 = fmaxf(fmaf(sc, f3.y, 1.0f), EPSc);
                acc += __log2f((a0 * a1) * (a2 * a3));
                acc += __log2f((a4 * a5) * (a6 * a7));
            }
            if (nxt) encode_store(nxt4, tid + 3 * NTH, g);
        }

        __syncthreads();   // buf k fully consumed; buf k+1 fully written
    }

    // ---- Block reduction ----
    float v = acc;
    #pragma unroll
    for (int o = 16; o; o >>= 1) v += __shfl_down_sync(0xFFFFFFFFu, v, o);
    const int wid = tid >> 5, lane = tid & 31;
    if (lane == 0) red[wid] = v;
    __syncthreads();
    if (wid == 0) {
        float w = (lane < NTH / 32) ? red[lane] : 0.0f;
        #pragma unroll
        for (int o = 16; o; o >>= 1) w += __shfl_down_sync(0xFFFFFFFFu, w, o);
        if (lane == 0) atomicAdd(&g_acc, (double)w);
    }

    // ---- Last-block-done: finalize + self-reset (graph-replayable) ----
    if (tid == 0) {
        __threadfence();
        unsigned int prev = atomicAdd(&g_cnt, 1u);
        if (prev == GRID - 1) {
            __threadfence();
            double S = *((volatile double*)&g_acc);
            // loss = 0.5*ln2*((M+K) - S/(B*T))
            double loss = 0.5 * 0.6931471805599453
                        * ((double)(Mc + Kc) - S / ((double)Bc * (double)Tc));
            out[0] = (float)loss;
            *((volatile double*)&g_acc) = 0.0;
            *((volatile unsigned int*)&g_cnt) = 0u;
            __threadfence();
        }
    }
}

extern "C" void kernel_launch(void* const* d_in, const int* in_sizes, int n_in,
                              void* d_out, int out_size) {
    const float* llrs        = (const float*)d_in[0];
    const int*   syndromes   = (const int*)d_in[1];
    const int*   observables = (const int*)d_in[2];
    const int*   chk_idx     = (const int*)d_in[3];
    // d_in[4] = chk_seg (unused: layout implied), d_in[5] = obs_idx, d_in[6] = obs_seg
    const int*   obs_idx     = (const int*)d_in[5];
    float* out = (float*)d_out;

    cudaFuncSetAttribute(decode_loss_kernel,
                         cudaFuncAttributeMaxDynamicSharedMemorySize, SMEM_BYTES);

    decode_loss_kernel<<<GRID, NTH, SMEM_BYTES>>>(
        llrs, syndromes, observables, chk_idx, obs_idx, out);
}

// round 11
// speedup vs baseline: 1.4657x; 1.4657x over previous
#include <cuda_runtime.h>
#include <cuda_fp16.h>
#include <cstdint>

// Problem constants (fixed by the reference)
#define Bc 128
#define Tc 30
#define Nc 10000
#define Mc 5000
#define Kc 10
#define CHK_W 6
#define OBS_W 50

#define NTH   1024
#define NPROD 512            // warps 0-15: producers
#define NCONS 512            // warps 16-31: consumers
#define RPC   8              // rows per chunk
#define NCH   4              // chunks per b (last has 6 rows)
#define NQ    2500           // float4 groups per row
#define NTASKS (Bc * NCH)    // 512 tasks
#define GRID  148            // persistent: one CTA per SM

// (128/127)^6 and (128/127)^50 de-scaling constants
#define SC6   1.04818341f
#define SC50  1.48016639f

// named barrier ids
#define BFULL0 2
#define BFULL1 3
#define BFREE0 4
#define BFREE1 5

// Shared memory layout (bytes)
// table: uint2 per position = 8 rows of biased-u8 tanh
#define OFF_BUF0 0
#define SZ_BUF   (Nc * 8)                    // 80000
#define OFF_BUF1 (OFF_BUF0 + SZ_BUF)         // 80000
#define OFF_CA   (OFF_BUF1 + SZ_BUF)         // 160000: u16 pair (i0,i1) per check
#define OFF_CB   (OFF_CA + Mc * 4)           // 180000: (i2,i3)
#define OFF_CC   (OFF_CB + Mc * 4)           // 200000: (i4,i5)
#define OFF_OIDX (OFF_CC + Mc * 4)           // 220000: u16[500]
#define OFF_RED  ((OFF_OIDX + Kc * OBS_W * 2 + 15) & ~15)
#define SMEM_BYTES (OFF_RED + 128)           // ~221136

__device__ double g_acc = 0.0;
__device__ unsigned int g_cnt = 0;

__device__ __forceinline__ __half2 H2(unsigned int u) {
    return *reinterpret_cast<const __half2*>(&u);
}
__device__ __forceinline__ unsigned int U2(__half2 h) {
    return *reinterpret_cast<const unsigned int*>(&h);
}
__device__ __forceinline__ unsigned int tanh_h2_u(__half2 v) {
    unsigned int r, x = U2(v);
    asm("tanh.approx.f16x2 %0, %1;" : "=r"(r) : "r"(x));
    return r;
}
__device__ __forceinline__ void bar_sync(int id) {
    asm volatile("bar.sync %0, %1;" :: "r"(id), "n"(NTH) : "memory");
}
__device__ __forceinline__ void bar_arrive(int id) {
    asm volatile("bar.arrive %0, %1;" :: "r"(id), "n"(NTH) : "memory");
}

// ---- encode: rows (a,b) f32 -> f16x2 word holding integers 1152+round(127*t)
__device__ __forceinline__ unsigned int enc_pair(float a, float b) {
    const __half2 h05  = __float2half2_rn(0.5f);
    const __half2 k127 = __float2half2_rn(127.0f);
    const __half2 b1152= __float2half2_rn(1152.0f);
    __half2 t = H2(tanh_h2_u(__hmul2(__floats2half2_rn(a, b), h05)));
    return U2(__hfma2(t, k127, b1152));   // halves in [1025,1279], integer-valued
}

// ---- decode: u32 of 4 biased bytes -> two half2 of t*127/128
#define CK   0x64646464u
__device__ __forceinline__ __half2 dec_lo(unsigned int a) {
    const __half2 mk = __float2half2_rn(0.0078125f);   // 2^-7
    const __half2 mb = __float2half2_rn(-9.0f);
    return __hfma2(H2(__byte_perm(a, CK, 0x4140)), mk, mb);
}
__device__ __forceinline__ __half2 dec_hi(unsigned int a) {
    const __half2 mk = __float2half2_rn(0.0078125f);
    const __half2 mb = __float2half2_rn(-9.0f);
    return __hfma2(H2(__byte_perm(a, CK, 0x4342)), mk, mb);
}

// ---- fp16 epilogue: 4 row-pair products + sign-scale -> sum of log2 over 8 rows
__device__ __forceinline__ float epi8(__half2 p01, __half2 p23, __half2 p45, __half2 p67,
                                      float sc) {
    const __half2 one2 = __float2half2_rn(1.0f);
    const __half2 eps2 = __float2half2_rn(6.103515625e-05f);  // 2^-14
    const __half2 sc2  = __float2half2_rn(sc);
    __half2 a01 = __hfma2(sc2, p01, one2);
    __half2 a23 = __hfma2(sc2, p23, one2);
    __half2 a45 = __hfma2(sc2, p45, one2);
    __half2 a67 = __hfma2(sc2, p67, one2);
    __half2 m = __hmul2(__hmul2(a01, a23), __hmul2(a45, a67));
    m = __hmax2(m, eps2);                 // finite-guard (never binds in practice)
    float2 f = __half22float2(m);
    return __log2f(f.x * f.y);
}

__global__ __launch_bounds__(NTH, 1)
void decode_loss_kernel(const float* __restrict__ llrs,
                        const int* __restrict__ syndromes,
                        const int* __restrict__ observables,
                        const int* __restrict__ chk_idx,
                        const int* __restrict__ obs_idx,
                        float* __restrict__ out) {
    extern __shared__ char smem[];
    uint2*          buf0 = (uint2*)(smem + OFF_BUF0);
    uint2*          buf1 = (uint2*)(smem + OFF_BUF1);
    unsigned int*   cA   = (unsigned int*)(smem + OFF_CA);
    unsigned int*   cB   = (unsigned int*)(smem + OFF_CB);
    unsigned int*   cC   = (unsigned int*)(smem + OFF_CC);
    unsigned short* oidx = (unsigned short*)(smem + OFF_OIDX);
    float*          red  = (float*)(smem + OFF_RED);

    const int cta = blockIdx.x;
    const int tid = threadIdx.x;
    const int ntasks = (NTASKS - cta + GRID - 1) / GRID;

    // ---- Stage (once per CTA): SoA u16-pair index arrays ----
    for (int m = tid; m < Mc; m += NTH) {
        const int2* c6 = (const int2*)(chk_idx + 6 * m);
        int2 p0 = __ldg(&c6[0]);
        int2 p1 = __ldg(&c6[1]);
        int2 p2 = __ldg(&c6[2]);
        cA[m] = (unsigned int)p0.x | ((unsigned int)p0.y << 16);
        cB[m] = (unsigned int)p1.x | ((unsigned int)p1.y << 16);
        cC[m] = (unsigned int)p2.x | ((unsigned int)p2.y << 16);
    }
    for (int i = tid; i < Kc * OBS_W; i += NTH)
        oidx[i] = (unsigned short)__ldg(&obs_idx[i]);
    __syncthreads();

    float acc = 0.0f;

    if (tid < NPROD) {
        // ================= PRODUCER (16 warps) =================
        const int tp = tid;
        for (int k = 0; k < ntasks; k++) {
            const int task = cta + k * GRID;
            const int b    = task >> 2;
            const int c    = task & 3;
            const int rows = min(RPC, Tc - RPC * c);
            if (k >= 2) bar_sync(BFREE0 + (k & 1));
            uint4* bf4 = (uint4*)((k & 1) ? buf1 : buf0);
            const float4* rb = (const float4*)(llrs + ((size_t)b * Tc + (size_t)RPC * c) * Nc);

            for (int q = tp; q < NQ; q += NPROD) {
                const float4 z = make_float4(0.f, 0.f, 0.f, 0.f);
                float4 v0 =              __ldg(&rb[0 * NQ + q]);
                float4 v1 = (rows > 1) ? __ldg(&rb[1 * NQ + q]) : z;
                float4 v2 = (rows > 2) ? __ldg(&rb[2 * NQ + q]) : z;
                float4 v3 = (rows > 3) ? __ldg(&rb[3 * NQ + q]) : z;
                float4 v4 = (rows > 4) ? __ldg(&rb[4 * NQ + q]) : z;
                float4 v5 = (rows > 5) ? __ldg(&rb[5 * NQ + q]) : z;
                float4 v6 = (rows > 6) ? __ldg(&rb[6 * NQ + q]) : z;
                float4 v7 = (rows > 7) ? __ldg(&rb[7 * NQ + q]) : z;

                unsigned int w01x = enc_pair(v0.x, v1.x), w23x = enc_pair(v2.x, v3.x);
                unsigned int w45x = enc_pair(v4.x, v5.x), w67x = enc_pair(v6.x, v7.x);
                unsigned int w01y = enc_pair(v0.y, v1.y), w23y = enc_pair(v2.y, v3.y);
                unsigned int w45y = enc_pair(v4.y, v5.y), w67y = enc_pair(v6.y, v7.y);
                unsigned int w01z = enc_pair(v0.z, v1.z), w23z = enc_pair(v2.z, v3.z);
                unsigned int w45z = enc_pair(v4.z, v5.z), w67z = enc_pair(v6.z, v7.z);
                unsigned int w01w = enc_pair(v0.w, v1.w), w23w = enc_pair(v2.w, v3.w);
                unsigned int w45w = enc_pair(v4.w, v5.w), w67w = enc_pair(v6.w, v7.w);

                uint4 o0, o1;
                o0.x = __byte_perm(w01x, w23x, 0x6420);   // pos 4q+0 rows0-3
                o0.y = __byte_perm(w45x, w67x, 0x6420);   // pos 4q+0 rows4-7
                o0.z = __byte_perm(w01y, w23y, 0x6420);
                o0.w = __byte_perm(w45y, w67y, 0x6420);
                o1.x = __byte_perm(w01z, w23z, 0x6420);
                o1.y = __byte_perm(w45z, w67z, 0x6420);
                o1.z = __byte_perm(w01w, w23w, 0x6420);
                o1.w = __byte_perm(w45w, w67w, 0x6420);
                bf4[2 * q]     = o0;
                bf4[2 * q + 1] = o1;
            }
            bar_arrive(BFULL0 + (k & 1));
        }
    } else {
        // ================= CONSUMER (16 warps) =================
        const int tc = tid - NPROD;
        for (int k = 0; k < ntasks; k++) {
            const int task = cta + k * GRID;
            const int b    = task >> 2;
            bar_sync(BFULL0 + (k & 1));
            const uint2* buf = (k & 1) ? buf1 : buf0;
            const int* syn = syndromes + (size_t)b * Mc;

            #pragma unroll 2
            for (int m = tc; m < Mc; m += NCONS) {
                unsigned int iA = cA[m];
                unsigned int iB = cB[m];
                unsigned int iC = cC[m];
                uint2 g0 = buf[iA & 0xFFFF];
                uint2 g1 = buf[iA >> 16];
                uint2 g2 = buf[iB & 0xFFFF];
                uint2 g3 = buf[iB >> 16];
                uint2 g4 = buf[iC & 0xFFFF];
                uint2 g5 = buf[iC >> 16];
                const float s = 1.0f - 2.0f * (float)__ldg(&syn[m]);

                __half2 p01 = __hmul2(__hmul2(dec_lo(g0.x), dec_lo(g1.x)),
                              __hmul2(__hmul2(dec_lo(g2.x), dec_lo(g3.x)),
                                      __hmul2(dec_lo(g4.x), dec_lo(g5.x))));
                __half2 p23 = __hmul2(__hmul2(dec_hi(g0.x), dec_hi(g1.x)),
                              __hmul2(__hmul2(dec_hi(g2.x), dec_hi(g3.x)),
                                      __hmul2(dec_hi(g4.x), dec_hi(g5.x))));
                __half2 p45 = __hmul2(__hmul2(dec_lo(g0.y), dec_lo(g1.y)),
                              __hmul2(__hmul2(dec_lo(g2.y), dec_lo(g3.y)),
                                      __hmul2(dec_lo(g4.y), dec_lo(g5.y))));
                __half2 p67 = __hmul2(__hmul2(dec_hi(g0.y), dec_hi(g1.y)),
                              __hmul2(__hmul2(dec_hi(g2.y), dec_hi(g3.y)),
                                      __hmul2(dec_hi(g4.y), dec_hi(g5.y))));

                acc += epi8(p01, p23, p45, p67, s * SC6);
            }

            if (tc < Kc) {
                const __half2 one2 = __float2half2_rn(1.0f);
                __half2 p01 = one2, p23 = one2, p45 = one2, p67 = one2;
                #pragma unroll
                for (int j = 0; j < OBS_W; j++) {
                    uint2 g = buf[oidx[tc * OBS_W + j]];
                    p01 = __hmul2(p01, dec_lo(g.x));
                    p23 = __hmul2(p23, dec_hi(g.x));
                    p45 = __hmul2(p45, dec_lo(g.y));
                    p67 = __hmul2(p67, dec_hi(g.y));
                }
                const float s = 1.0f - 2.0f * (float)__ldg(&observables[(size_t)b * Kc + tc]);
                acc += epi8(p01, p23, p45, p67, s * SC50);
            }

            if (k < ntasks - 2) bar_arrive(BFREE0 + (k & 1));
        }
    }

    // ---- Block reduction (producers contribute 0) ----
    __syncthreads();
    float v = acc;
    #pragma unroll
    for (int o = 16; o; o >>= 1) v += __shfl_down_sync(0xFFFFFFFFu, v, o);
    const int wid = tid >> 5, lane = tid & 31;
    if (lane == 0) red[wid] = v;
    __syncthreads();
    if (wid == 0) {
        float w = (lane < NTH / 32) ? red[lane] : 0.0f;
        #pragma unroll
        for (int o = 16; o; o >>= 1) w += __shfl_down_sync(0xFFFFFFFFu, w, o);
        if (lane == 0) atomicAdd(&g_acc, (double)w);
    }

    // ---- Last-block-done: finalize + self-reset (graph-replayable) ----
    if (tid == 0) {
        __threadfence();
        unsigned int prev = atomicAdd(&g_cnt, 1u);
        if (prev == GRID - 1) {
            __threadfence();
            double S = *((volatile double*)&g_acc);
            // loss = 0.5*ln2*((M+K) - S/(B*T))
            double loss = 0.5 * 0.6931471805599453
                        * ((double)(Mc + Kc) - S / ((double)Bc * (double)Tc));
            out[0] = (float)loss;
            *((volatile double*)&g_acc) = 0.0;
            *((volatile unsigned int*)&g_cnt) = 0u;
            __threadfence();
        }
    }
}

extern "C" void kernel_launch(void* const* d_in, const int* in_sizes, int n_in,
                              void* d_out, int out_size) {
    const float* llrs        = (const float*)d_in[0];
    const int*   syndromes   = (const int*)d_in[1];
    const int*   observables = (const int*)d_in[2];
    const int*   chk_idx     = (const int*)d_in[3];
    // d_in[4] = chk_seg (unused: layout implied), d_in[5] = obs_idx, d_in[6] = obs_seg
    const int*   obs_idx     = (const int*)d_in[5];
    float* out = (float*)d_out;

    cudaFuncSetAttribute(decode_loss_kernel,
                         cudaFuncAttributeMaxDynamicSharedMemorySize, SMEM_BYTES);

    decode_loss_kernel<<<GRID, NTH, SMEM_BYTES>>>(
        llrs, syndromes, observables, chk_idx, obs_idx, out);
}

// round 12
// speedup vs baseline: 1.6064x; 1.0960x over previous
#include <cuda_runtime.h>
#include <cuda_fp16.h>
#include <cstdint>

// Problem constants (fixed by the reference)
#define Bc 128
#define Tc 30
#define Nc 10000
#define Mc 5000
#define Kc 10
#define CHK_W 6
#define OBS_W 50
#define EPSc 1e-6f

#define NTH   1024
#define NPROD 512            // warps 0-15: producers
#define NCONS 512            // warps 16-31: consumers
#define RPC   8              // rows per chunk
#define NCH   4              // chunks per b (last has 6 rows)
#define NQ    2500           // float4 groups per row
#define NTASKS (Bc * NCH)    // 512 tasks
#define GRID  148            // persistent: one CTA per SM

// (128/127)^6 and (128/127)^50 de-scaling constants
#define SC6   1.04818341f
#define SC50  1.48016639f

// named barrier ids
#define BFULL0 2
#define BFULL1 3
#define BFREE0 4
#define BFREE1 5

// Shared memory layout (bytes)
// table: uint2 per position = 8 rows of biased-u8 tanh
#define OFF_BUF0 0
#define SZ_BUF   (Nc * 8)                    // 80000
#define OFF_BUF1 (OFF_BUF0 + SZ_BUF)         // 80000
#define OFF_CA   (OFF_BUF1 + SZ_BUF)         // 160000: u16 pair (i0,i1) per check
#define OFF_CB   (OFF_CA + Mc * 4)           // 180000: (i2,i3)
#define OFF_CC   (OFF_CB + Mc * 4)           // 200000: (i4,i5)
#define OFF_OIDX (OFF_CC + Mc * 4)           // 220000: u16[500]
#define OFF_SYN0 (OFF_OIDX + Kc * OBS_W * 2) // 221000: s8 signs, buffer 0 task
#define OFF_SYN1 (OFF_SYN0 + Mc)             // 226000: s8 signs, buffer 1 task
#define OFF_RED  ((OFF_SYN1 + Mc + 15) & ~15)
#define SMEM_BYTES (OFF_RED + 128)           // ~231136 (< 232448 cap)

__device__ double g_acc = 0.0;
__device__ unsigned int g_cnt = 0;

__device__ __forceinline__ __half2 H2(unsigned int u) {
    return *reinterpret_cast<const __half2*>(&u);
}
__device__ __forceinline__ unsigned int U2(__half2 h) {
    return *reinterpret_cast<const unsigned int*>(&h);
}
__device__ __forceinline__ unsigned int tanh_h2_u(__half2 v) {
    unsigned int r, x = U2(v);
    asm("tanh.approx.f16x2 %0, %1;" : "=r"(r) : "r"(x));
    return r;
}
__device__ __forceinline__ void bar_sync(int id) {
    asm volatile("bar.sync %0, %1;" :: "r"(id), "n"(NTH) : "memory");
}
__device__ __forceinline__ void bar_arrive(int id) {
    asm volatile("bar.arrive %0, %1;" :: "r"(id), "n"(NTH) : "memory");
}

// ---- encode: rows (a,b) f32 -> f16x2 word holding integers 1152+round(127*t)
__device__ __forceinline__ unsigned int enc_pair(float a, float b) {
    const __half2 h05  = __float2half2_rn(0.5f);
    const __half2 k127 = __float2half2_rn(127.0f);
    const __half2 b1152= __float2half2_rn(1152.0f);
    __half2 t = H2(tanh_h2_u(__hmul2(__floats2half2_rn(a, b), h05)));
    return U2(__hfma2(t, k127, b1152));   // halves in [1025,1279], integer-valued
}

// ---- decode: u32 of 4 biased bytes -> two half2 of t*127/128
#define CK   0x64646464u
__device__ __forceinline__ __half2 dec_lo(unsigned int a) {
    const __half2 mk = __float2half2_rn(0.0078125f);   // 2^-7
    const __half2 mb = __float2half2_rn(-9.0f);
    return __hfma2(H2(__byte_perm(a, CK, 0x4140)), mk, mb);
}
__device__ __forceinline__ __half2 dec_hi(unsigned int a) {
    const __half2 mk = __float2half2_rn(0.0078125f);
    const __half2 mb = __float2half2_rn(-9.0f);
    return __hfma2(H2(__byte_perm(a, CK, 0x4342)), mk, mb);
}

__global__ __launch_bounds__(NTH, 1)
void decode_loss_kernel(const float* __restrict__ llrs,
                        const int* __restrict__ syndromes,
                        const int* __restrict__ observables,
                        const int* __restrict__ chk_idx,
                        const int* __restrict__ obs_idx,
                        float* __restrict__ out) {
    extern __shared__ char smem[];
    uint2*          buf0 = (uint2*)(smem + OFF_BUF0);
    uint2*          buf1 = (uint2*)(smem + OFF_BUF1);
    unsigned int*   cA   = (unsigned int*)(smem + OFF_CA);
    unsigned int*   cB   = (unsigned int*)(smem + OFF_CB);
    unsigned int*   cC   = (unsigned int*)(smem + OFF_CC);
    unsigned short* oidx = (unsigned short*)(smem + OFF_OIDX);
    signed char*    syn0 = (signed char*)(smem + OFF_SYN0);
    signed char*    syn1 = (signed char*)(smem + OFF_SYN1);
    float*          red  = (float*)(smem + OFF_RED);

    const int cta = blockIdx.x;
    const int tid = threadIdx.x;
    const int ntasks = (NTASKS - cta + GRID - 1) / GRID;

    // ---- Stage (once per CTA): SoA u16-pair index arrays ----
    for (int m = tid; m < Mc; m += NTH) {
        const int2* c6 = (const int2*)(chk_idx + 6 * m);
        int2 p0 = __ldg(&c6[0]);
        int2 p1 = __ldg(&c6[1]);
        int2 p2 = __ldg(&c6[2]);
        cA[m] = (unsigned int)p0.x | ((unsigned int)p0.y << 16);
        cB[m] = (unsigned int)p1.x | ((unsigned int)p1.y << 16);
        cC[m] = (unsigned int)p2.x | ((unsigned int)p2.y << 16);
    }
    for (int i = tid; i < Kc * OBS_W; i += NTH)
        oidx[i] = (unsigned short)__ldg(&obs_idx[i]);
    __syncthreads();

    float acc = 0.0f;

    if (tid < NPROD) {
        // ================= PRODUCER (16 warps) =================
        const int tp = tid;
        for (int k = 0; k < ntasks; k++) {
            const int task = cta + k * GRID;
            const int b    = task >> 2;
            const int c    = task & 3;
            const int rows = min(RPC, Tc - RPC * c);
            if (k >= 2) bar_sync(BFREE0 + (k & 1));
            uint4* bf4 = (uint4*)((k & 1) ? buf1 : buf0);
            signed char* ss = (k & 1) ? syn1 : syn0;
            const float4* rb = (const float4*)(llrs + ((size_t)b * Tc + (size_t)RPC * c) * Nc);

            // stage this task's syndrome signs (s8, int4-vectorized: ~3 iters)
            {
                const int4* sg = (const int4*)(syndromes + (size_t)b * Mc);
                char4* sd = (char4*)ss;
                for (int i = tp; i < Mc / 4; i += NPROD) {
                    int4 v = __ldg(&sg[i]);
                    char4 o;
                    o.x = (signed char)(1 - 2 * v.x);
                    o.y = (signed char)(1 - 2 * v.y);
                    o.z = (signed char)(1 - 2 * v.z);
                    o.w = (signed char)(1 - 2 * v.w);
                    sd[i] = o;
                }
            }

            for (int q = tp; q < NQ; q += NPROD) {
                const float4 z = make_float4(0.f, 0.f, 0.f, 0.f);
                float4 v0 =              __ldg(&rb[0 * NQ + q]);
                float4 v1 = (rows > 1) ? __ldg(&rb[1 * NQ + q]) : z;
                float4 v2 = (rows > 2) ? __ldg(&rb[2 * NQ + q]) : z;
                float4 v3 = (rows > 3) ? __ldg(&rb[3 * NQ + q]) : z;
                float4 v4 = (rows > 4) ? __ldg(&rb[4 * NQ + q]) : z;
                float4 v5 = (rows > 5) ? __ldg(&rb[5 * NQ + q]) : z;
                float4 v6 = (rows > 6) ? __ldg(&rb[6 * NQ + q]) : z;
                float4 v7 = (rows > 7) ? __ldg(&rb[7 * NQ + q]) : z;

                unsigned int w01x = enc_pair(v0.x, v1.x), w23x = enc_pair(v2.x, v3.x);
                unsigned int w45x = enc_pair(v4.x, v5.x), w67x = enc_pair(v6.x, v7.x);
                unsigned int w01y = enc_pair(v0.y, v1.y), w23y = enc_pair(v2.y, v3.y);
                unsigned int w45y = enc_pair(v4.y, v5.y), w67y = enc_pair(v6.y, v7.y);
                unsigned int w01z = enc_pair(v0.z, v1.z), w23z = enc_pair(v2.z, v3.z);
                unsigned int w45z = enc_pair(v4.z, v5.z), w67z = enc_pair(v6.z, v7.z);
                unsigned int w01w = enc_pair(v0.w, v1.w), w23w = enc_pair(v2.w, v3.w);
                unsigned int w45w = enc_pair(v4.w, v5.w), w67w = enc_pair(v6.w, v7.w);

                uint4 o0, o1;
                o0.x = __byte_perm(w01x, w23x, 0x6420);   // pos 4q+0 rows0-3
                o0.y = __byte_perm(w45x, w67x, 0x6420);   // pos 4q+0 rows4-7
                o0.z = __byte_perm(w01y, w23y, 0x6420);
                o0.w = __byte_perm(w45y, w67y, 0x6420);
                o1.x = __byte_perm(w01z, w23z, 0x6420);
                o1.y = __byte_perm(w45z, w67z, 0x6420);
                o1.z = __byte_perm(w01w, w23w, 0x6420);
                o1.w = __byte_perm(w45w, w67w, 0x6420);
                bf4[2 * q]     = o0;
                bf4[2 * q + 1] = o1;
            }
            bar_arrive(BFULL0 + (k & 1));
        }
    } else {
        // ================= CONSUMER (16 warps) =================
        const int tc = tid - NPROD;
        for (int k = 0; k < ntasks; k++) {
            const int task = cta + k * GRID;
            const int b    = task >> 2;
            bar_sync(BFULL0 + (k & 1));
            const uint2* buf = (k & 1) ? buf1 : buf0;
            const signed char* ss = (k & 1) ? syn1 : syn0;

            #pragma unroll 2
            for (int m = tc; m < Mc; m += NCONS) {
                unsigned int iA = cA[m];
                unsigned int iB = cB[m];
                unsigned int iC = cC[m];
                uint2 g0 = buf[iA & 0xFFFF];
                uint2 g1 = buf[iA >> 16];
                uint2 g2 = buf[iB & 0xFFFF];
                uint2 g3 = buf[iB >> 16];
                uint2 g4 = buf[iC & 0xFFFF];
                uint2 g5 = buf[iC >> 16];
                const float s  = (float)ss[m];          // LDS, not L2
                const float sc = s * SC6;

                __half2 p01 = __hmul2(__hmul2(dec_lo(g0.x), dec_lo(g1.x)),
                              __hmul2(__hmul2(dec_lo(g2.x), dec_lo(g3.x)),
                                      __hmul2(dec_lo(g4.x), dec_lo(g5.x))));
                __half2 p23 = __hmul2(__hmul2(dec_hi(g0.x), dec_hi(g1.x)),
                              __hmul2(__hmul2(dec_hi(g2.x), dec_hi(g3.x)),
                                      __hmul2(dec_hi(g4.x), dec_hi(g5.x))));
                __half2 p45 = __hmul2(__hmul2(dec_lo(g0.y), dec_lo(g1.y)),
                              __hmul2(__hmul2(dec_lo(g2.y), dec_lo(g3.y)),
                                      __hmul2(dec_lo(g4.y), dec_lo(g5.y))));
                __half2 p67 = __hmul2(__hmul2(dec_hi(g0.y), dec_hi(g1.y)),
                              __hmul2(__hmul2(dec_hi(g2.y), dec_hi(g3.y)),
                                      __hmul2(dec_hi(g4.y), dec_hi(g5.y))));

                float2 f0 = __half22float2(p01);
                float2 f1 = __half22float2(p23);
                float2 f2 = __half22float2(p45);
                float2 f3 = __half22float2(p67);

                float a0 = fmaxf(fmaf(sc, f0.x, 1.0f), EPSc);
                float a1 = fmaxf(fmaf(sc, f0.y, 1.0f), EPSc);
                float a2 = fmaxf(fmaf(sc, f1.x, 1.0f), EPSc);
                float a3 = fmaxf(fmaf(sc, f1.y, 1.0f), EPSc);
                float a4 = fmaxf(fmaf(sc, f2.x, 1.0f), EPSc);
                float a5 = fmaxf(fmaf(sc, f2.y, 1.0f), EPSc);
                float a6 = fmaxf(fmaf(sc, f3.x, 1.0f), EPSc);
                float a7 = fmaxf(fmaf(sc, f3.y, 1.0f), EPSc);
                acc += __log2f((a0 * a1) * (a2 * a3));
                acc += __log2f((a4 * a5) * (a6 * a7));
            }

            if (tc < Kc) {
                const __half2 one2 = __float2half2_rn(1.0f);
                __half2 p01 = one2, p23 = one2, p45 = one2, p67 = one2;
                #pragma unroll
                for (int j = 0; j < OBS_W; j++) {
                    uint2 g = buf[oidx[tc * OBS_W + j]];
                    p01 = __hmul2(p01, dec_lo(g.x));
                    p23 = __hmul2(p23, dec_hi(g.x));
                    p45 = __hmul2(p45, dec_lo(g.y));
                    p67 = __hmul2(p67, dec_hi(g.y));
                }
                const float s  = 1.0f - 2.0f * (float)__ldg(&observables[(size_t)b * Kc + tc]);
                const float sc = s * SC50;
                float2 f0 = __half22float2(p01);
                float2 f1 = __half22float2(p23);
                float2 f2 = __half22float2(p45);
                float2 f3 = __half22float2(p67);
                float a0 = fmaxf(fmaf(sc, f0.x, 1.0f), EPSc);
                float a1 = fmaxf(fmaf(sc, f0.y, 1.0f), EPSc);
                float a2 = fmaxf(fmaf(sc, f1.x, 1.0f), EPSc);
                float a3 = fmaxf(fmaf(sc, f1.y, 1.0f), EPSc);
                float a4 = fmaxf(fmaf(sc, f2.x, 1.0f), EPSc);
                float a5 = fmaxf(fmaf(sc, f2.y, 1.0f), EPSc);
                float a6 = fmaxf(fmaf(sc, f3.x, 1.0f), EPSc);
                float a7 = fmaxf(fmaf(sc, f3.y, 1.0f), EPSc);
                acc += __log2f((a0 * a1) * (a2 * a3));
                acc += __log2f((a4 * a5) * (a6 * a7));
            }

            if (k < ntasks - 2) bar_arrive(BFREE0 + (k & 1));
        }
    }

    // ---- Block reduction (producers contribute 0) ----
    __syncthreads();
    float v = acc;
    #pragma unroll
    for (int o = 16; o; o >>= 1) v += __shfl_down_sync(0xFFFFFFFFu, v, o);
    const int wid = tid >> 5, lane = tid & 31;
    if (lane == 0) red[wid] = v;
    __syncthreads();
    if (wid == 0) {
        float w = (lane < NTH / 32) ? red[lane] : 0.0f;
        #pragma unroll
        for (int o = 16; o; o >>= 1) w += __shfl_down_sync(0xFFFFFFFFu, w, o);
        if (lane == 0) atomicAdd(&g_acc, (double)w);
    }

    // ---- Last-block-done: finalize + self-reset (graph-replayable) ----
    if (tid == 0) {
        __threadfence();
        unsigned int prev = atomicAdd(&g_cnt, 1u);
        if (prev == GRID - 1) {
            __threadfence();
            double S = *((volatile double*)&g_acc);
            // loss = 0.5*ln2*((M+K) - S/(B*T))
            double loss = 0.5 * 0.6931471805599453
                        * ((double)(Mc + Kc) - S / ((double)Bc * (double)Tc));
            out[0] = (float)loss;
            *((volatile double*)&g_acc) = 0.0;
            *((volatile unsigned int*)&g_cnt) = 0u;
            __threadfence();
        }
    }
}

extern "C" void kernel_launch(void* const* d_in, const int* in_sizes, int n_in,
                              void* d_out, int out_size) {
    const float* llrs        = (const float*)d_in[0];
    const int*   syndromes   = (const int*)d_in[1];
    const int*   observables = (const int*)d_in[2];
    const int*   chk_idx     = (const int*)d_in[3];
    // d_in[4] = chk_seg (unused: layout implied), d_in[5] = obs_idx, d_in[6] = obs_seg
    const int*   obs_idx     = (const int*)d_in[5];
    float* out = (float*)d_out;

    cudaFuncSetAttribute(decode_loss_kernel,
                         cudaFuncAttributeMaxDynamicSharedMemorySize, SMEM_BYTES);

    decode_loss_kernel<<<GRID, NTH, SMEM_BYTES>>>(
        llrs, syndromes, observables, chk_idx, obs_idx, out);
}